// round 16
// baseline (speedup 1.0000x reference)
#include <cuda_runtime.h>
#include <climits>

// InstanceDiceLoss — 4 graph-captured kernels.
// Histogram is SLOT-indexed (per-sample); rank remap happens in the dice
// tail, eliminating the separate rank kernel.
// Natural mask layout: word(g) = g>>5, bit(g) = g&31.

#define VOXB 21
#define VOX (1 << VOXB)            // 128^3
#define NVOL 4                     // gt_s0, gt_s1, pr_s0, pr_s1
#define TOTV (NVOL * VOX)
#define NWORD (TOTV / 32)
#define MAXLAB 64
#define MM 65

#define K1_BLK 256
#define K1_THR 1024
#define K2_BLK 512
#define K2_THR 256
#define K4_BLK 64
#define K4_THR 1024
#define K4_NT (K4_BLK * K4_THR)

__device__ int      d_W[TOTV];             // union-find parent (active only)
__device__ int      d_A[TOTV];             // per-root max initial id
__device__ int      d_slot[TOTV];          // per-root slot in rootList
__device__ unsigned d_mask[NWORD];         // foreground bitmask
__device__ int      d_active[TOTV];        // active voxel list (global ids)
__device__ int      d_activeCnt = 0;
__device__ int      d_rootCnt[NVOL] = {0, 0, 0, 0};
__device__ int      d_rootList[NVOL * MAXLAB];
__device__ unsigned d_ov[2 * MM * MM];     // per-sample slot-indexed hists
__device__ unsigned d_doneCnt = 0;

__device__ __forceinline__ unsigned mask_test(const unsigned* mk, int g) {
    return (mk[g >> 5] >> (g & 31)) & 1u;
}

// ECL-CC representative walk with path compression via plain stores.
__device__ __forceinline__ int rep(int* W, int v) {
    int curr = W[v];
    if (curr != v) {
        int prev = v, next;
        while (curr > (next = W[curr])) {
            W[prev] = next;
            prev = curr;
            curr = next;
        }
    }
    return curr;
}

// ECL-CC union: CAS only on roots.
__device__ __forceinline__ void join(int* W, int a, int b) {
    int vs = rep(W, a), os = rep(W, b);
    bool repeat;
    do {
        repeat = false;
        if (vs != os) {
            int ret;
            if (vs < os) {
                if ((ret = atomicCAS(&W[os], os, vs)) != os) { os = ret; repeat = true; }
            } else {
                if ((ret = atomicCAS(&W[vs], vs, os)) != vs) { vs = ret; repeat = true; }
            }
        }
    } while (repeat);
}

// ---- k1: coalesced threshold -> mask + UF init + active list ----
__global__ void __launch_bounds__(K1_THR, 1)
k1_init(const float* __restrict__ x, const float* __restrict__ y) {
    const int lane   = threadIdx.x & 31;
    const int warpId = (blockIdx.x * K1_THR + threadIdx.x) >> 5;  // == tile

    int g0 = warpId << 10;
    const float4* b4 = (g0 < 2 * VOX) ? (const float4*)(y + g0)
                                      : (const float4*)(x + (g0 - 2 * VOX));
    float4 v[8];
    #pragma unroll
    for (int j = 0; j < 8; j++)            // MLP = 8 coalesced 512B loads
        v[j] = b4[j * 32 + lane];

    unsigned nib[8];
    int cnt = 0;
    #pragma unroll
    for (int j = 0; j < 8; j++) {
        nib[j] = (v[j].x > 0.5f ? 1u : 0u) | (v[j].y > 0.5f ? 2u : 0u) |
                 (v[j].z > 0.5f ? 4u : 0u) | (v[j].w > 0.5f ? 8u : 0u);
        cnt += __popc(nib[j]);
    }

    #pragma unroll
    for (int j = 0; j < 8; j++) {
        unsigned w = nib[j] << (4 * (lane & 7));
        w |= __shfl_xor_sync(0xffffffffu, w, 1);
        w |= __shfl_xor_sync(0xffffffffu, w, 2);
        w |= __shfl_xor_sync(0xffffffffu, w, 4);
        if ((lane & 7) == 0)
            d_mask[(g0 >> 5) + 4 * j + (lane >> 3)] = w;
    }

    if (__ballot_sync(0xffffffffu, cnt > 0)) {
        unsigned p = (unsigned)cnt;        // inclusive warp scan
        #pragma unroll
        for (int d = 1; d < 32; d <<= 1) {
            unsigned t = __shfl_up_sync(0xffffffffu, p, d);
            if (lane >= d) p += t;
        }
        unsigned base;
        if (lane == 31) base = (unsigned)atomicAdd(&d_activeCnt, (int)p);
        base = __shfl_sync(0xffffffffu, base, 31);
        int idx = (int)base + (int)p - cnt;
        #pragma unroll
        for (int j = 0; j < 8; j++) {
            unsigned ww = nib[j];
            while (ww) {
                int c = __ffs(ww) - 1;
                ww &= ww - 1u;
                int gid = g0 + 128 * j + 4 * lane + c;
                d_W[gid] = gid & (VOX - 1);
                d_A[gid] = 0;
                d_active[idx++] = gid;
            }
        }
    }
}

// ---- k2: pruned union over forward 26-neighborhood ----
__global__ void __launch_bounds__(K2_THR)
k2_merge() {
    const int n = d_activeCnt;
    for (int t = blockIdx.x * K2_THR + threadIdx.x; t < n;
         t += gridDim.x * K2_THR) {
        int gid = d_active[t];
        int vol = gid >> VOXB;
        int local = gid & (VOX - 1);
        int* W = d_W + (vol << VOXB);
        const unsigned* mk = d_mask + (vol << (VOXB - 5));
        int z = local >> 14, yy = (local >> 7) & 127, xx = local & 127;

        bool e = xx < 127 && mask_test(mk, local + 1);
        bool w = xx > 0   && mask_test(mk, local - 1);
        bool nn = yy < 127 && mask_test(mk, local + 128);
        bool s = yy > 0   && mask_test(mk, local - 128);
        bool u = z < 127  && mask_test(mk, local + 16384);

        if (e)  join(W, local, local + 1);
        if (nn) join(W, local, local + 128);
        if (u)  join(W, local, local + 16384);

        if (yy < 127) {
            if (xx < 127 && !(e | nn) && mask_test(mk, local + 129))
                join(W, local, local + 129);
            if (xx > 0 && !(w | nn) && mask_test(mk, local + 127))
                join(W, local, local + 127);
        }
        if (z < 127) {
            int b = local + 16384;
            if (xx < 127 && !(e | u) && mask_test(mk, b + 1)) join(W, local, b + 1);
            if (xx > 0   && !(w | u) && mask_test(mk, b - 1)) join(W, local, b - 1);
            if (yy < 127 && !(nn | u) && mask_test(mk, b + 128)) join(W, local, b + 128);
            if (yy > 0   && !(s | u)  && mask_test(mk, b - 128)) join(W, local, b - 128);
            if (xx < 127 && yy < 127 && !(e | nn | u) && mask_test(mk, b + 129))
                join(W, local, b + 129);
            if (xx < 127 && yy > 0 && !(e | s | u) && mask_test(mk, b - 127))
                join(W, local, b - 127);
            if (xx > 0 && yy < 127 && !(w | nn | u) && mask_test(mk, b + 127))
                join(W, local, b + 127);
            if (xx > 0 && yy > 0 && !(w | s | u) && mask_test(mk, b - 129))
                join(W, local, b - 129);
        }
    }
}

// ---- k3: flatten to final root, per-root maxid, root list + slot ----
__global__ void __launch_bounds__(K2_THR)
k3_flatten() {
    const int n = d_activeCnt;
    for (int t = blockIdx.x * K2_THR + threadIdx.x; t < n;
         t += gridDim.x * K2_THR) {
        int gid = d_active[t];
        int vol = gid >> VOXB;
        int local = gid & (VOX - 1);
        int* W = d_W + (vol << VOXB);
        int r = local, p = W[r];
        while (p != r) { r = p; p = W[r]; }
        d_W[gid] = r;
        atomicMax(&d_A[(vol << VOXB) + r], local + 1);
        if (r == local) {
            int slot = atomicAdd(&d_rootCnt[vol], 1);
            if (slot < MAXLAB) {
                d_rootList[vol * MAXLAB + slot] = local;
                d_slot[gid] = slot;          // root -> slot map for hist
            }
        }
    }
}

// ---- k4: slot-indexed per-sample smem hists + last-block rank/dice ----
__global__ void __launch_bounds__(K4_THR, 1)
k4_finish(float* __restrict__ out) {
    const int tid = blockIdx.x * K4_THR + threadIdx.x;
    __shared__ unsigned s_h[2 * MM * MM];    // [sample][gslot+1][pslot+1]
    for (int i = threadIdx.x; i < 2 * MM * MM; i += K4_THR) s_h[i] = 0u;
    __syncthreads();

    const int n = d_activeCnt;
    for (int t = tid; t < n; t += K4_NT) {
        int gid = d_active[t];
        int vol = gid >> VOXB;
        int local = gid & (VOX - 1);
        if (vol < 2) {                       // gt voxel of sample `vol`
            int g = d_slot[(vol << VOXB) + d_W[gid]] + 1;
            int pg = ((vol + 2) << VOXB) + local;
            int p = mask_test(d_mask, pg)
                        ? d_slot[((vol + 2) << VOXB) + d_W[pg]] + 1 : 0;
            atomicAdd(&s_h[vol * MM * MM + g * MM + p], 1u);
        } else {                             // pr voxel where gt is bg: (0, p)
            int gg = ((vol - 2) << VOXB) + local;
            if (!mask_test(d_mask, gg)) {
                int p = d_slot[(vol << VOXB) + d_W[gid]] + 1;
                atomicAdd(&s_h[(vol - 2) * MM * MM + p], 1u);
            }
        }
    }
    __syncthreads();
    for (int i = threadIdx.x; i < 2 * MM * MM; i += K4_THR) {
        unsigned c = s_h[i];
        if (c) atomicAdd(&d_ov[i], c);
    }

    // arrive-only completion: last block computes ranks, merges, dices
    __syncthreads();
    __shared__ int s_last;
    if (threadIdx.x == 0) {
        __threadfence();
        s_last = (atomicAdd(&d_doneCnt, 1u) == K4_BLK - 1) ? 1 : 0;
    }
    __syncthreads();
    if (!s_last) return;
    __threadfence();

    {
        __shared__ int s_rm[NVOL][MM];       // slot+1 -> rank+1 per volume
        __shared__ int s_mx[NVOL][MAXLAB];
        __shared__ unsigned s_M[MM * MM];    // merged rank-indexed matrix
        __shared__ float prs[MM], dice_s[MM], gts_s[MM];
        __shared__ int fp_s[MM], tp_s[MM];
        int t = threadIdx.x;

        // slot -> rank map (4 vols x 64 slots on first 256 threads)
        {
            int vol = (t >> 6) & (NVOL - 1), i = t & 63;
            int k = 0, m = INT_MAX;
            if (t < NVOL * MAXLAB) {
                k = d_rootCnt[vol];
                if (k > MAXLAB) k = MAXLAB;
                if (i < k)
                    m = d_A[(vol << VOXB) + d_rootList[vol * MAXLAB + i]];
                s_mx[vol][i] = m;
                if (i == 0) s_rm[vol][0] = 0;   // background stays 0
            }
        }
        for (int i = t; i < MM * MM; i += K4_THR) s_M[i] = 0u;
        __syncthreads();
        {
            int vol = (t >> 6) & (NVOL - 1), i = t & 63;
            if (t < NVOL * MAXLAB) {
                int k = d_rootCnt[vol];
                if (k > MAXLAB) k = MAXLAB;
                if (i < k) {
                    int m = s_mx[vol][i];
                    int rank = 0;
                    #pragma unroll 8
                    for (int j = 0; j < MAXLAB; j++)
                        rank += (s_mx[vol][j] < m) ? 1 : 0;
                    s_rm[vol][i + 1] = rank + 1;
                }
            }
        }
        __syncthreads();

        // merge both samples' slot hists into rank-indexed matrix
        for (int s = 0; s < 2; s++) {
            for (int i = t; i < MM * MM; i += K4_THR) {
                unsigned c = d_ov[s * MM * MM + i];
                if (c) {
                    int g = i / MM, p = i % MM;
                    atomicAdd(&s_M[s_rm[s][g] * MM + s_rm[s + 2][p]], c);
                }
            }
        }
        __syncthreads();

        // dice from merged smem matrix
        if (t < MM) {
            float sm = 0.f; int any = 0;
            for (int g = 0; g < MM; g++) {
                unsigned c = s_M[g * MM + t];
                sm += (float)c;
                if (g >= 1) any |= (c > 0u);
            }
            prs[t] = sm; tp_s[t] = any;
        }
        __syncthreads();
        if (t >= 1 && t < MM) {
            float inter = 0.f, uni = 0.f;
            float gts = (float)s_M[t * MM + 0];
            for (int p = 1; p < MM; p++) {
                unsigned c = s_M[t * MM + p];
                float cf = (float)c;
                inter += cf; gts += cf;
                if (c > 0u) uni += prs[p];
            }
            float d = (inter > 0.f) ? 2.f * inter / fmaxf(uni + gts, 1.f) : 0.f;
            dice_s[t] = d; gts_s[t] = gts;
            fp_s[t] = (prs[t] > 0.f && !tp_s[t]) ? 1 : 0;
        }
        __syncthreads();
        if (t == 0) {
            float ld = 0.f, ng = 0.f, nf = 0.f;
            for (int g = 1; g < MM; g++) {
                ld += dice_s[g];
                ng += (gts_s[g] > 0.f) ? 1.f : 0.f;
                nf += (float)fp_s[g];
            }
            out[0] = ld / (ng + nf);
        }
        __syncthreads();
        // self-clean for next replay
        for (int i = t; i < 2 * MM * MM; i += K4_THR) d_ov[i] = 0u;
        if (t == 0) { d_activeCnt = 0; d_doneCnt = 0; }
        if (t < NVOL) d_rootCnt[t] = 0;
    }
}

extern "C" void kernel_launch(void* const* d_in, const int* in_sizes, int n_in,
                              void* d_out, int out_size) {
    const float* x = (const float*)d_in[0];
    const float* y = (const float*)d_in[1];
    k1_init<<<K1_BLK, K1_THR>>>(x, y);
    k2_merge<<<K2_BLK, K2_THR>>>();
    k3_flatten<<<K2_BLK, K2_THR>>>();
    k4_finish<<<K4_BLK, K4_THR>>>((float*)d_out);
}

// round 17
// speedup vs baseline: 1.0617x; 1.0617x over previous
#include <cuda_runtime.h>
#include <climits>

// InstanceDiceLoss — 5 graph-captured kernels, single-wave grid geometry.
// Natural mask layout: word(g) = g>>5, bit(g) = g&31.

#define VOXB 21
#define VOX (1 << VOXB)            // 128^3
#define NVOL 4                     // gt_s0, gt_s1, pr_s0, pr_s1
#define TOTV (NVOL * VOX)
#define NWORD (TOTV / 32)
#define MAXLAB 64
#define MM 65
#define NTILE (TOTV / 1024)        // 8192 warp tiles

#define K1_BLK 1024                // 1024 x 256 = 8192 warps = NTILE, 1 wave
#define K1_THR 256
#define K2_BLK 232                 // 232 x 256 = 59392 ~= n, 1 wave
#define K2_THR 256
#define K4_BLK 64
#define K4_THR 1024
#define K4_NT (K4_BLK * K4_THR)

__device__ int      d_W[TOTV];             // union-find parent (active only)
__device__ int      d_A[TOTV];             // per-root max initial id
__device__ int      d_rank[TOTV];          // per-root compact id (1..k)
__device__ unsigned d_mask[NWORD];         // foreground bitmask
__device__ int      d_active[TOTV];        // active voxel list (global ids)
__device__ int      d_activeCnt = 0;
__device__ int      d_rootCnt[NVOL] = {0, 0, 0, 0};
__device__ int      d_rootList[NVOL * MAXLAB];
__device__ unsigned d_ov[MM * MM];         // zero-init (static) + tail reset
__device__ unsigned d_doneCnt = 0;

__device__ __forceinline__ unsigned mask_test(const unsigned* mk, int g) {
    return (mk[g >> 5] >> (g & 31)) & 1u;
}

// ECL-CC representative walk with path compression via plain stores.
__device__ __forceinline__ int rep(int* W, int v) {
    int curr = W[v];
    if (curr != v) {
        int prev = v, next;
        while (curr > (next = W[curr])) {
            W[prev] = next;
            prev = curr;
            curr = next;
        }
    }
    return curr;
}

// ECL-CC union: CAS only on roots.
__device__ __forceinline__ void join(int* W, int a, int b) {
    int vs = rep(W, a), os = rep(W, b);
    bool repeat;
    do {
        repeat = false;
        if (vs != os) {
            int ret;
            if (vs < os) {
                if ((ret = atomicCAS(&W[os], os, vs)) != os) { os = ret; repeat = true; }
            } else {
                if ((ret = atomicCAS(&W[vs], vs, os)) != vs) { vs = ret; repeat = true; }
            }
        }
    } while (repeat);
}

// ---- k1: coalesced threshold -> mask + UF init + active list ----
__global__ void __launch_bounds__(K1_THR, 8)
k1_init(const float* __restrict__ x, const float* __restrict__ y) {
    const int lane   = threadIdx.x & 31;
    const int warpId = (blockIdx.x * K1_THR + threadIdx.x) >> 5;  // == tile

    int g0 = warpId << 10;
    const float4* b4 = (g0 < 2 * VOX) ? (const float4*)(y + g0)
                                      : (const float4*)(x + (g0 - 2 * VOX));
    float4 v[8];
    #pragma unroll
    for (int j = 0; j < 8; j++)            // MLP = 8 coalesced 512B loads
        v[j] = b4[j * 32 + lane];

    unsigned nib[8];
    int cnt = 0;
    #pragma unroll
    for (int j = 0; j < 8; j++) {
        nib[j] = (v[j].x > 0.5f ? 1u : 0u) | (v[j].y > 0.5f ? 2u : 0u) |
                 (v[j].z > 0.5f ? 4u : 0u) | (v[j].w > 0.5f ? 8u : 0u);
        cnt += __popc(nib[j]);
    }

    // natural-layout mask words via 3 shuffle-XORs per 8-lane group
    #pragma unroll
    for (int j = 0; j < 8; j++) {
        unsigned w = nib[j] << (4 * (lane & 7));
        w |= __shfl_xor_sync(0xffffffffu, w, 1);
        w |= __shfl_xor_sync(0xffffffffu, w, 2);
        w |= __shfl_xor_sync(0xffffffffu, w, 4);
        if ((lane & 7) == 0)
            d_mask[(g0 >> 5) + 4 * j + (lane >> 3)] = w;
    }

    if (__ballot_sync(0xffffffffu, cnt > 0)) {
        unsigned p = (unsigned)cnt;        // inclusive warp scan
        #pragma unroll
        for (int d = 1; d < 32; d <<= 1) {
            unsigned t = __shfl_up_sync(0xffffffffu, p, d);
            if (lane >= d) p += t;
        }
        unsigned base;
        if (lane == 31) base = (unsigned)atomicAdd(&d_activeCnt, (int)p);
        base = __shfl_sync(0xffffffffu, base, 31);
        int idx = (int)base + (int)p - cnt;
        #pragma unroll
        for (int j = 0; j < 8; j++) {
            unsigned ww = nib[j];
            while (ww) {
                int c = __ffs(ww) - 1;
                ww &= ww - 1u;
                int gid = g0 + 128 * j + 4 * lane + c;
                d_W[gid] = gid & (VOX - 1);
                d_A[gid] = 0;
                d_active[idx++] = gid;
            }
        }
    }
}

// ---- k2: pruned union over forward 26-neighborhood ----
__global__ void __launch_bounds__(K2_THR)
k2_merge() {
    const int n = d_activeCnt;
    for (int t = blockIdx.x * K2_THR + threadIdx.x; t < n;
         t += K2_BLK * K2_THR) {
        int gid = d_active[t];
        int vol = gid >> VOXB;
        int local = gid & (VOX - 1);
        int* W = d_W + (vol << VOXB);
        const unsigned* mk = d_mask + (vol << (VOXB - 5));
        int z = local >> 14, yy = (local >> 7) & 127, xx = local & 127;

        bool e = xx < 127 && mask_test(mk, local + 1);
        bool w = xx > 0   && mask_test(mk, local - 1);
        bool nn = yy < 127 && mask_test(mk, local + 128);
        bool s = yy > 0   && mask_test(mk, local - 128);
        bool u = z < 127  && mask_test(mk, local + 16384);

        if (e)  join(W, local, local + 1);
        if (nn) join(W, local, local + 128);
        if (u)  join(W, local, local + 16384);

        if (yy < 127) {
            if (xx < 127 && !(e | nn) && mask_test(mk, local + 129))
                join(W, local, local + 129);
            if (xx > 0 && !(w | nn) && mask_test(mk, local + 127))
                join(W, local, local + 127);
        }
        if (z < 127) {
            int b = local + 16384;
            if (xx < 127 && !(e | u) && mask_test(mk, b + 1)) join(W, local, b + 1);
            if (xx > 0   && !(w | u) && mask_test(mk, b - 1)) join(W, local, b - 1);
            if (yy < 127 && !(nn | u) && mask_test(mk, b + 128)) join(W, local, b + 128);
            if (yy > 0   && !(s | u)  && mask_test(mk, b - 128)) join(W, local, b - 128);
            if (xx < 127 && yy < 127 && !(e | nn | u) && mask_test(mk, b + 129))
                join(W, local, b + 129);
            if (xx < 127 && yy > 0 && !(e | s | u) && mask_test(mk, b - 127))
                join(W, local, b - 127);
            if (xx > 0 && yy < 127 && !(w | nn | u) && mask_test(mk, b + 127))
                join(W, local, b + 127);
            if (xx > 0 && yy > 0 && !(w | s | u) && mask_test(mk, b - 129))
                join(W, local, b - 129);
        }
    }
}

// ---- k3: flatten to final root, per-root maxid, root list ----
__global__ void __launch_bounds__(K2_THR)
k3_flatten() {
    const int n = d_activeCnt;
    for (int t = blockIdx.x * K2_THR + threadIdx.x; t < n;
         t += K2_BLK * K2_THR) {
        int gid = d_active[t];
        int vol = gid >> VOXB;
        int local = gid & (VOX - 1);
        int* W = d_W + (vol << VOXB);
        int r = local, p = W[r];
        while (p != r) { r = p; p = W[r]; }
        d_W[gid] = r;
        atomicMax(&d_A[(vol << VOXB) + r], local + 1);
        if (r == local) {
            int slot = atomicAdd(&d_rootCnt[vol], 1);
            if (slot < MAXLAB) d_rootList[vol * MAXLAB + slot] = local;
        }
    }
}

// ---- k3b: compact ids = rank of component maxid (ONE block) ----
__global__ void k3b_rank() {
    __shared__ int s_mx[NVOL][MAXLAB];
    int t = threadIdx.x;                     // 256 threads = 4 vols x 64
    int vol = t >> 6, i = t & 63;
    int k = d_rootCnt[vol];
    if (k > MAXLAB) k = MAXLAB;
    int root = -1, m = INT_MAX;
    if (i < k) {
        root = d_rootList[vol * MAXLAB + i];
        m = d_A[(vol << VOXB) + root];
    }
    s_mx[vol][i] = m;
    __syncthreads();
    if (i < k) {
        int rank = 0;
        #pragma unroll 8
        for (int j = 0; j < MAXLAB; j++)
            rank += (s_mx[vol][j] < m) ? 1 : 0;   // maxids unique
        d_rank[(vol << VOXB) + root] = rank + 1;
    }
}

// ---- k4: smem histogram + last-block dice + self-clean ----
__global__ void __launch_bounds__(K4_THR, 1)
k4_finish(float* __restrict__ out) {
    const int tid = blockIdx.x * K4_THR + threadIdx.x;
    __shared__ unsigned s_ov[MM * MM];
    for (int i = threadIdx.x; i < MM * MM; i += K4_THR) s_ov[i] = 0u;
    __syncthreads();

    const int n = d_activeCnt;
    for (int t = tid; t < n; t += K4_NT) {
        int gid = d_active[t];
        int vol = gid >> VOXB;
        int local = gid & (VOX - 1);
        if (vol < 2) {                       // gt voxel: record (g, p)
            int g = d_rank[(vol << VOXB) + d_W[gid]];
            int pg = ((vol + 2) << VOXB) + local;
            int p = mask_test(d_mask, pg)
                        ? d_rank[((vol + 2) << VOXB) + d_W[pg]] : 0;
            atomicAdd(&s_ov[g * MM + p], 1u);
        } else {                             // pr voxel where gt is bg: (0, p)
            int gg = ((vol - 2) << VOXB) + local;
            if (!mask_test(d_mask, gg)) {
                int p = d_rank[(vol << VOXB) + d_W[gid]];
                atomicAdd(&s_ov[p], 1u);
            }
        }
    }
    __syncthreads();
    for (int i = threadIdx.x; i < MM * MM; i += K4_THR) {
        unsigned c = s_ov[i];
        if (c) atomicAdd(&d_ov[i], c);
    }

    // arrive-only completion: last block computes dice + self-cleans
    __syncthreads();
    __shared__ int s_last;
    if (threadIdx.x == 0) {
        __threadfence();
        s_last = (atomicAdd(&d_doneCnt, 1u) == K4_BLK - 1) ? 1 : 0;
    }
    __syncthreads();
    if (!s_last) return;
    __threadfence();

    {
        __shared__ float prs[MM], dice_s[MM], gts_s[MM];
        __shared__ int fp_s[MM], tp_s[MM];
        int t = threadIdx.x;
        if (t < MM) {
            float sm = 0.f; int any = 0;
            for (int g = 0; g < MM; g++) {
                unsigned c = d_ov[g * MM + t];
                sm += (float)c;
                if (g >= 1) any |= (c > 0u);
            }
            prs[t] = sm; tp_s[t] = any;
        }
        __syncthreads();
        if (t >= 1 && t < MM) {
            float inter = 0.f, uni = 0.f;
            float gts = (float)d_ov[t * MM + 0];
            for (int p = 1; p < MM; p++) {
                unsigned c = d_ov[t * MM + p];
                float cf = (float)c;
                inter += cf; gts += cf;
                if (c > 0u) uni += prs[p];
            }
            float d = (inter > 0.f) ? 2.f * inter / fmaxf(uni + gts, 1.f) : 0.f;
            dice_s[t] = d; gts_s[t] = gts;
            fp_s[t] = (prs[t] > 0.f && !tp_s[t]) ? 1 : 0;
        }
        __syncthreads();
        if (t == 0) {
            float ld = 0.f, ng = 0.f, nf = 0.f;
            for (int g = 1; g < MM; g++) {
                ld += dice_s[g];
                ng += (gts_s[g] > 0.f) ? 1.f : 0.f;
                nf += (float)fp_s[g];
            }
            out[0] = ld / (ng + nf);
        }
        __syncthreads();
        // self-clean for next replay
        for (int i = threadIdx.x; i < MM * MM; i += K4_THR) d_ov[i] = 0u;
        if (t == 0) { d_activeCnt = 0; d_doneCnt = 0; }
        if (t < NVOL) d_rootCnt[t] = 0;
    }
}

extern "C" void kernel_launch(void* const* d_in, const int* in_sizes, int n_in,
                              void* d_out, int out_size) {
    const float* x = (const float*)d_in[0];
    const float* y = (const float*)d_in[1];
    k1_init<<<K1_BLK, K1_THR>>>(x, y);
    k2_merge<<<K2_BLK, K2_THR>>>();
    k3_flatten<<<K2_BLK, K2_THR>>>();
    k3b_rank<<<1, 256>>>();
    k4_finish<<<K4_BLK, K4_THR>>>((float*)d_out);
}